// round 17
// baseline (speedup 1.0000x reference)
#include <cuda_runtime.h>
#include <cuda_fp16.h>
#include <cstdint>
#include <cstddef>

// out = x @ Wv^T + bv.  (Reference's softmax rows sum to 1 => its final
// einsum('btu,btj->btj', weights, v) == v + rounding; Q/K/softmax are dead.)
//
// Single-pass fp16 GEMM M=8192, K=1024, N=64 on portable mma.sync m16n8k16.
// R17: x streamed as CONTIGUOUS full-K 64KB tiles (16 rows x 4KB adjacent),
// pipelined across tiles: grid 128, each CTA does 4 M-tiles with double-
// buffered cp.async (compute tile i overlaps the linear 64KB load of i+1).
// Tests the hypothesis that the 2.7 TB/s wall is the strided 512B x 4KB
// chunk pattern of R13-R15. 8 warps = 2N x 4K-split; W frags from L2-hot
// g_wf in double-buffered registers (R16 path). Reduction scratch dedicated.

#define NEMB    1024
#define NH      64
#define MT      16
#define THREADS 256
#define GRID    128              // 128 CTAs x 4 tiles x 16 rows = 8192
#define XPW     1032             // fp32 words per smem row (4128B; LDS.64 conflict-free)
#define XBUF_W  (MT * XPW)       // 16512 words
#define XBUF_B  (XBUF_W * 4)     // 66048 bytes
#define RED_OFF (2 * XBUF_B)     // 132096
#define RED_WRD 3840             // 3 ksets x 2 wn x 32 lanes x 20
#define SMEM_BYTES (RED_OFF + RED_WRD * 4)   // 147456

static_assert(SMEM_BYTES <= 227328, "fits sm_103a smem");

// W fragments (layout proven R9-R16): g_wf[s*128 + (wn*2+p)*32 + lane]
__device__ uint4 g_wf[8192];

__global__ void wconv(const float* __restrict__ W)
{
    int id   = blockIdx.x * blockDim.x + threadIdx.x;   // 0..8191
    int lane = id & 31;
    int p    = (id >> 5) & 1;
    int wn   = (id >> 6) & 1;
    int s    = id >> 7;
    int k    = s * 16 + (lane & 3) * 2;
    int j0   = wn * 4 + p * 2;
    uint4 o;
#pragma unroll
    for (int jj = 0; jj < 2; jj++) {
        int n = (j0 + jj) * 8 + (lane >> 2);
        const float* ptr = W + (size_t)n * NEMB + k;
        __half2 h0 = __float22half2_rn(make_float2(ptr[0], ptr[1]));
        __half2 h1 = __float22half2_rn(make_float2(ptr[8], ptr[9]));
        if (jj == 0) { o.x = *(uint32_t*)&h0; o.y = *(uint32_t*)&h1; }
        else         { o.z = *(uint32_t*)&h0; o.w = *(uint32_t*)&h1; }
    }
    g_wf[id] = o;
}

__device__ __forceinline__ void mma16816(float* c,
                                         uint32_t a0, uint32_t a1, uint32_t a2, uint32_t a3,
                                         uint32_t b0, uint32_t b1)
{
    asm volatile(
        "mma.sync.aligned.m16n8k16.row.col.f32.f16.f16.f32 "
        "{%0,%1,%2,%3}, {%4,%5,%6,%7}, {%8,%9}, {%0,%1,%2,%3};"
        : "+f"(c[0]), "+f"(c[1]), "+f"(c[2]), "+f"(c[3])
        : "r"(a0), "r"(a1), "r"(a2), "r"(a3), "r"(b0), "r"(b1));
}

__device__ __forceinline__ void cp16(uint32_t s, const void* g)
{
    asm volatile("cp.async.cg.shared.global [%0], [%1], 16;" :: "r"(s), "l"(g));
}

__device__ __forceinline__ uint32_t packh2(float a, float b)
{
    __half2 h = __float22half2_rn(make_float2(a, b));
    return *(uint32_t*)&h;
}

__shared__ float bias_s[NH];
extern __shared__ char smem[];

// compute + epilogue for one tile (buffer and tilebase runtime; frag slots
// become compile-time after full unroll)
__device__ __forceinline__ void do_tile(const float* xb, float* red,
                                        float* __restrict__ out, int tilebase,
                                        int kq, int wn, int lid)
{
    const int wbase  = wn * 64 + lid;
    const int khbase = kq * 16;
    const int abase  = (lid >> 2) * XPW + (lid & 3) * 2;

    float acc[4][4];
#pragma unroll
    for (int j = 0; j < 4; j++)
#pragma unroll
        for (int e = 0; e < 4; e++) acc[j][e] = 0.0f;

    uint4 w0[2][2], w1[2][2];
#pragma unroll
    for (int b = 0; b < 2; b++) {
        const int s0 = khbase + b * 2;
        w0[b][0] = g_wf[s0 * 128 + wbase];
        w1[b][0] = g_wf[s0 * 128 + wbase + 32];
        w0[b][1] = g_wf[(s0 + 1) * 128 + wbase];
        w1[b][1] = g_wf[(s0 + 1) * 128 + wbase + 32];
    }

#pragma unroll
    for (int g = 0; g < 8; g++) {
        uint32_t a0[2], a1[2], a2[2], a3[2];
#pragma unroll
        for (int sl = 0; sl < 2; sl++) {
            const int sabs = khbase + g * 2 + sl;
            const float* ap = xb + abase + sabs * 16;
            float2 f0 = *(const float2*)ap;
            float2 f1 = *(const float2*)(ap + 8 * XPW);
            float2 f2 = *(const float2*)(ap + 8);
            float2 f3 = *(const float2*)(ap + 8 * XPW + 8);
            a0[sl] = packh2(f0.x, f0.y);
            a1[sl] = packh2(f1.x, f1.y);
            a2[sl] = packh2(f2.x, f2.y);
            a3[sl] = packh2(f3.x, f3.y);
        }
#pragma unroll
        for (int sl = 0; sl < 2; sl++) {
            mma16816(acc[0], a0[sl], a1[sl], a2[sl], a3[sl], w0[g & 1][sl].x, w0[g & 1][sl].y);
            mma16816(acc[1], a0[sl], a1[sl], a2[sl], a3[sl], w0[g & 1][sl].z, w0[g & 1][sl].w);
            mma16816(acc[2], a0[sl], a1[sl], a2[sl], a3[sl], w1[g & 1][sl].x, w1[g & 1][sl].y);
            mma16816(acc[3], a0[sl], a1[sl], a2[sl], a3[sl], w1[g & 1][sl].z, w1[g & 1][sl].w);
        }
        // refill buffer g&1 with group g+2
        if (g + 2 < 8) {
            const int s0 = khbase + (g + 2) * 2;
            w0[g & 1][0] = g_wf[s0 * 128 + wbase];
            w1[g & 1][0] = g_wf[s0 * 128 + wbase + 32];
            w0[g & 1][1] = g_wf[(s0 + 1) * 128 + wbase];
            w1[g & 1][1] = g_wf[(s0 + 1) * 128 + wbase + 32];
        }
    }

    __syncthreads();                      // all MMA reads done; gate red writes
    if (kq > 0) {
        const int rbase = (((kq - 1) * 2 + wn) * 32 + lid) * 20;
#pragma unroll
        for (int j = 0; j < 4; j++)
            *(float4*)(red + rbase + j * 4) = *(float4*)acc[j];
    }
    __syncthreads();
    if (kq == 0) {
        const int orow = tilebase + (lid >> 2);
#pragma unroll
        for (int j = 0; j < 4; j++) {
            float4 s1 = *(float4*)(red + ((0 * 2 + wn) * 32 + lid) * 20 + j * 4);
            float4 s2 = *(float4*)(red + ((1 * 2 + wn) * 32 + lid) * 20 + j * 4);
            float4 s3 = *(float4*)(red + ((2 * 2 + wn) * 32 + lid) * 20 + j * 4);
            const int col = wn * 32 + j * 8 + ((lid & 3) << 1);
            const float b0 = bias_s[col], b1 = bias_s[col + 1];
            float2 lo = make_float2(acc[j][0] + s1.x + s2.x + s3.x + b0,
                                    acc[j][1] + s1.y + s2.y + s3.y + b1);
            float2 hi = make_float2(acc[j][2] + s1.z + s2.z + s3.z + b0,
                                    acc[j][3] + s1.w + s2.w + s3.w + b1);
            *(float2*)(out + (size_t)orow * NH + col)       = lo;
            *(float2*)(out + (size_t)(orow + 8) * NH + col) = hi;
        }
    }
}

__global__ void __launch_bounds__(THREADS)
vproj(const float* __restrict__ x, const float* __restrict__ bv,
      float* __restrict__ out)
{
    const int t   = threadIdx.x;
    const int wid = t >> 5;
    const int lid = t & 31;
    const int kq  = wid >> 1;         // K quarter
    const int wn  = wid & 1;          // N half
    const int tile0 = blockIdx.x << 2;

    float* xsm = (float*)smem;
    float* red = (float*)(smem + RED_OFF);
    const uint32_t xsm_s = (uint32_t)__cvta_generic_to_shared(xsm);

    if (t < 16) ((float4*)bias_s)[t] = ((const float4*)bv)[t];

    // producer mapping: row16 = t>>4 (0..15), seg = t&15 (16B unit); each
    // thread copies 16 x 16B at 256B stride => tile = contiguous 64KB walk
    const int row16 = t >> 4;
    const int seg   = t & 15;

#define GCOPY(i)                                                            \
    {                                                                       \
        if ((i) < 4) {                                                      \
            const char* src = (const char*)(x + ((size_t)(tile0 + (i)) * MT \
                              + row16) * NEMB) + seg * 16;                  \
            const uint32_t dst = xsm_s + (uint32_t)(((i) & 1) * XBUF_B      \
                              + row16 * (XPW * 4) + seg * 16);              \
            _Pragma("unroll")                                               \
            for (int s_ = 0; s_ < 16; s_++)                                 \
                cp16(dst + (uint32_t)(s_ * 256), src + s_ * 256);           \
        }                                                                   \
        asm volatile("cp.async.commit_group;");                             \
    }

    GCOPY(0)

    GCOPY(1)
    asm volatile("cp.async.wait_group 1;");
    __syncthreads();
    do_tile(xsm + 0 * XBUF_W, red, out, (tile0 + 0) * MT, kq, wn, lid);

    GCOPY(2)
    asm volatile("cp.async.wait_group 1;");
    __syncthreads();
    do_tile(xsm + 1 * XBUF_W, red, out, (tile0 + 1) * MT, kq, wn, lid);

    GCOPY(3)
    asm volatile("cp.async.wait_group 1;");
    __syncthreads();
    do_tile(xsm + 0 * XBUF_W, red, out, (tile0 + 2) * MT, kq, wn, lid);

    GCOPY(4)   // empty commit keeps wait literals simple
    asm volatile("cp.async.wait_group 0;");
    __syncthreads();
    do_tile(xsm + 1 * XBUF_W, red, out, (tile0 + 3) * MT, kq, wn, lid);
#undef GCOPY
}

extern "C" void kernel_launch(void* const* d_in, const int* in_sizes, int n_in,
                              void* d_out, int out_size)
{
    const float* x  = (const float*)d_in[0];
    const float* Wv = (const float*)d_in[5];
    const float* bv = (const float*)d_in[6];

    cudaFuncSetAttribute(vproj, cudaFuncAttributeMaxDynamicSharedMemorySize, SMEM_BYTES);
    wconv<<<32, 256>>>(Wv);
    vproj<<<GRID, THREADS, SMEM_BYTES>>>(x, bv, (float*)d_out);
}